// round 9
// baseline (speedup 1.0000x reference)
#include <cuda_runtime.h>
#include <math.h>
#include <stdint.h>

#define NN   32768
#define EE   1048576
#define NSD  64
#define NVD  32
#define LATD 256

// ---- scales ----
#define INV8    0.125f                 // 1/sqrt(64)
#define C1      0.10206207261596575f   // (1/sqrt(3))/sqrt(32) = 1/sqrt(96)
#define INV_R2  0.7071067811865476f
#define INVS32  0.17677669529663687f   // 1/sqrt(32)
#define S_USS   0.011048543456039806f  // 1/(64*sqrt(2))
#define S_UVV   0.012757998811063534f  // 1/(32*sqrt(6))
#define S_V     0.015625f              // 1/sqrt(64*32*2) = 1/64

typedef unsigned long long ull;

// ---- scratch (device globals; no allocation) ----
__device__ float g_ns[NN * NSD];
__device__ float g_nv[NN * NVD * 3];
__device__ float g_NF[(size_t)NN * 384];  // SS(64)|Q(3x64)|SV(32)|VS(3x32)
__device__ float g_as[NN * NSD];
__device__ float g_av[NN * NVD * 3];

__device__ __forceinline__ float sigmf(float x) { return 1.0f / (1.0f + __expf(-x)); }

// ---- packed f32x2 helpers ----
__device__ __forceinline__ void ffma2(ull& d, ull a, ull b) {
    asm("fma.rn.f32x2 %0, %1, %2, %0;" : "+l"(d) : "l"(a), "l"(b));
}
__device__ __forceinline__ ull fmul2(ull a, ull b) {
    ull r; asm("mul.rn.f32x2 %0, %1, %2;" : "=l"(r) : "l"(a), "l"(b)); return r;
}
__device__ __forceinline__ ull fadd2(ull a, ull b) {
    ull r; asm("add.rn.f32x2 %0, %1, %2;" : "=l"(r) : "l"(a), "l"(b)); return r;
}
__device__ __forceinline__ ull pack2(float x, float y) {
    ull r;
    asm("mov.b64 %0, {%1, %2};" : "=l"(r)
        : "r"(__float_as_uint(x)), "r"(__float_as_uint(y)));
    return r;
}
__device__ __forceinline__ float2 unpack2(ull v) {
    unsigned int lo, hi;
    asm("mov.b64 {%0, %1}, %2;" : "=r"(lo), "=r"(hi) : "l"(v));
    return make_float2(__uint_as_float(lo), __uint_as_float(hi));
}

// ============================ k_in: ns = x @ W_in / 8 ============================
__global__ __launch_bounds__(256) void k_in(const float* __restrict__ x,
                                            const float* __restrict__ Win) {
    __shared__ float xs[32 * 65];
    __shared__ float ws[64 * 64];
    const int tid = threadIdx.x;
    const int node0 = blockIdx.x * 32;
    const float4* wg = (const float4*)Win;
    float4* ws4 = (float4*)ws;
#pragma unroll
    for (int r = 0; r < 4; r++) ws4[tid + r * 256] = wg[tid + r * 256];
#pragma unroll
    for (int r = 0; r < 8; r++) {
        int lin = tid + r * 256; int t = lin >> 6, i = lin & 63;
        xs[t * 65 + i] = x[(size_t)(node0 + t) * 64 + i];
    }
    __syncthreads();
    const int o = tid & 63, tq = tid >> 6;
    float acc[8] = {0, 0, 0, 0, 0, 0, 0, 0};
#pragma unroll 16
    for (int i = 0; i < 64; i++) {
        float w = ws[i * 64 + o];
#pragma unroll
        for (int tt = 0; tt < 8; tt++) acc[tt] += xs[(tq * 8 + tt) * 65 + i] * w;
    }
#pragma unroll
    for (int tt = 0; tt < 8; tt++)
        g_ns[(size_t)(node0 + tq * 8 + tt) * 64 + o] = acc[tt] * INV8;
}

// ============== k_feat: per-node precompute SS, Q, SV, VS ==============
__global__ __launch_bounds__(256) void k_feat(const float* __restrict__ Wss,
                                              const float* __restrict__ Wvv0,
                                              const float* __restrict__ Wsv,
                                              const float* __restrict__ Wvs) {
    __shared__ float s_wss[64 * 64];
    __shared__ float s_wvv[32 * 64];
    __shared__ float s_wsv[64 * 32];
    __shared__ float s_wvs[32 * 32];
    __shared__ float s_ns[8][64];
    __shared__ float s_nv[8][96];
    const int tid = threadIdx.x;
    for (int i = tid; i < 4096; i += 256) s_wss[i] = Wss[i];
    for (int i = tid; i < 2048; i += 256) s_wvv[i] = Wvv0[i];
    for (int i = tid; i < 2048; i += 256) s_wsv[i] = Wsv[i];
    for (int i = tid; i < 1024; i += 256) s_wvs[i] = Wvs[i];
    const int w = tid >> 5, lane = tid & 31;
    const int node = blockIdx.x * 8 + w;
#pragma unroll
    for (int r = 0; r < 2; r++) s_ns[w][lane + 32 * r] = g_ns[(size_t)node * 64 + lane + 32 * r];
#pragma unroll
    for (int r = 0; r < 3; r++) s_nv[w][lane + 32 * r] = g_nv[(size_t)node * 96 + lane + 32 * r];
    __syncthreads();
    float* nf = g_NF + (size_t)node * 384;
#pragma unroll
    for (int h = 0; h < 2; h++) {
        int o = lane + 32 * h;
        float a = 0;
#pragma unroll 8
        for (int i = 0; i < 64; i++) a += s_ns[w][i] * s_wss[i * 64 + o];
        nf[o] = a;
    }
#pragma unroll
    for (int xx = 0; xx < 3; xx++) {
#pragma unroll
        for (int h = 0; h < 2; h++) {
            int o = lane + 32 * h;
            float a = 0;
#pragma unroll 8
            for (int m = 0; m < 32; m++) a += s_nv[w][m * 3 + xx] * s_wvv[m * 64 + o];
            nf[64 + xx * 64 + o] = a;
        }
    }
    {
        float a = 0;
#pragma unroll 8
        for (int i = 0; i < 64; i++) a += s_ns[w][i] * s_wsv[i * 32 + lane];
        nf[256 + lane] = a;
    }
#pragma unroll
    for (int xx = 0; xx < 3; xx++) {
        float a = 0;
#pragma unroll 8
        for (int m = 0; m < 32; m++) a += s_nv[w][m * 3 + xx] * s_wvs[m * 32 + lane];
        nf[288 + xx * 32 + lane] = a;
    }
}

// ================= k_edge: per-edge message + gate + scatter-add =================
__global__ __launch_bounds__(256) void k_edge(const float* __restrict__ eattr,
                                              const int* __restrict__ eidx,
                                              const float* __restrict__ gmw,
                                              const float* __restrict__ gmb) {
    __shared__ float s_gw[96], s_gb[96];
    const int tid = threadIdx.x;
    if (tid < 96) { s_gw[tid] = gmw[tid]; s_gb[tid] = gmb[tid]; }
    __syncthreads();
    const int w = tid >> 5, lane = tid & 31;
    const int e = blockIdx.x * 8 + w;
    const int r = eidx[e];
    const int c = eidx[EE + e];
    const float ev0 = eattr[(size_t)e * 4 + 0];
    const float ev1 = eattr[(size_t)e * 4 + 1];
    const float ev2 = eattr[(size_t)e * 4 + 2];
    const float es  = eattr[(size_t)e * 4 + 3];
    const float* nf = g_NF + (size_t)c * 384;
    float ms[2];
#pragma unroll
    for (int h = 0; h < 2; h++) {
        int o = lane + 32 * h;
        float dot = ev0 * nf[64 + o] + ev1 * nf[128 + o] + ev2 * nf[192 + o];
        float v = (es * nf[o] * INV8 + dot * C1) * INV_R2;
        ms[h] = v * sigmf(v);
    }
    const float sv = nf[256 + lane];
    float mv0 = (sv * ev0 * INV8 + es * nf[288 + lane] * INVS32) * INV_R2;
    float mv1 = (sv * ev1 * INV8 + es * nf[320 + lane] * INVS32) * INV_R2;
    float mv2 = (sv * ev2 * INV8 + es * nf[352 + lane] * INVS32) * INV_R2;
    float p = mv0 + mv1 + mv2;
#pragma unroll
    for (int off = 16; off; off >>= 1) p += __shfl_xor_sync(0xffffffffu, p, off);
    const float mean = p * (1.0f / 96.0f);
    const float g0 = sigmf(mean * s_gw[lane * 3 + 0] + s_gb[lane * 3 + 0]);
    const float g1 = sigmf(mean * s_gw[lane * 3 + 1] + s_gb[lane * 3 + 1]);
    const float g2 = sigmf(mean * s_gw[lane * 3 + 2] + s_gb[lane * 3 + 2]);
    float* as = g_as + (size_t)r * 64;
    float* av = g_av + (size_t)r * 96;
    atomicAdd(as + lane,        ms[0]);
    atomicAdd(as + lane + 32,   ms[1]);
    atomicAdd(av + lane * 3 + 0, mv0 * g0);
    atomicAdd(av + lane * 3 + 1, mv1 * g1);
    atomicAdd(av + lane * 3 + 2, mv2 * g2);
}

// ====== k_bilin: four bilinears + gate + residual ======
// 64 nodes / block, 256 threads, 2 blocks/SM (108KB smem each).
// Features TRANSPOSED in smem: feat-major, 64 nodes contiguous.
// Phase A: f32x2 lanes = 2 outs; A stored pre-duplicated -> zero movs in main loop.
// Phase B: one GEMM with rows = (node-pair, x): M=96 pairs, N=32, f32x2 lanes = node pair.
// smem floats: ns_T 4096 | as_T 4096 | nv_T 6144 | av_T 6144 | scratch 7168 = 27648
#define BILIN_SMEM (27648 * 4)

__global__ __launch_bounds__(256, 2) void k_bilin(const float* __restrict__ Wuss,
                                                  const float* __restrict__ Wuvv,
                                                  const float* __restrict__ Wusv,
                                                  const float* __restrict__ Wuvs,
                                                  const float* __restrict__ guw,
                                                  const float* __restrict__ gub) {
    extern __shared__ float sm[];
    float* ns_T = sm;            // [64 i][64 t]
    float* as_T = sm + 4096;     // [64 j][64 t]
    float* nv_T = sm + 8192;     // [96 row = x*32+m][64 t]
    float* av_T = sm + 14336;    // [96][64]
    float* scr  = sm + 20480;    // 7168 floats scratch
    const int tid = threadIdx.x;
    const int node0 = blockIdx.x * 64;

    // ---- load node data transposed ----
    {
        const float4* gns = (const float4*)(g_ns + (size_t)node0 * 64);
        const float4* gas = (const float4*)(g_as + (size_t)node0 * 64);
#pragma unroll
        for (int r = 0; r < 4; r++) {
            int lin = tid + r * 256;       // 1024 float4
            int t = lin >> 4, c = (lin & 15) * 4;
            float4 v = gns[lin], u = gas[lin];
            ns_T[(c + 0) * 64 + t] = v.x; ns_T[(c + 1) * 64 + t] = v.y;
            ns_T[(c + 2) * 64 + t] = v.z; ns_T[(c + 3) * 64 + t] = v.w;
            as_T[(c + 0) * 64 + t] = u.x; as_T[(c + 1) * 64 + t] = u.y;
            as_T[(c + 2) * 64 + t] = u.z; as_T[(c + 3) * 64 + t] = u.w;
        }
        const float4* gnv = (const float4*)(g_nv + (size_t)node0 * 96);
        const float4* gav = (const float4*)(g_av + (size_t)node0 * 96);
#pragma unroll
        for (int r = 0; r < 6; r++) {
            int lin = tid + r * 256;       // 1536 float4
            int t = lin / 24, cq = (lin % 24) * 4;
            float4 v = gnv[lin], u = gav[lin];
            float vv[4] = {v.x, v.y, v.z, v.w};
            float uu[4] = {u.x, u.y, u.z, u.w};
#pragma unroll
            for (int q = 0; q < 4; q++) {
                int f = cq + q;                    // f = m*3 + x
                int row = (f % 3) * 32 + (f / 3);  // x*32 + m
                nv_T[row * 64 + t] = vv[q];
                av_T[row * 64 + t] = uu[q];
            }
        }
    }
    __syncthreads();

    // ================ Phase A: u_s = uss + uvv ================
    // thread: outs 8*ogA..+7 (4 out-pairs), nodes 2*ngA, 2*ngA+1
    const int ogA = tid & 7;
    const int ngA = tid >> 3;
    float* WsA = scr;            // [32 kk][64 o]
    float* AsA = scr + 2048;     // [32 kk][128 = dup 64 t]
    ull acc[8];
#pragma unroll
    for (int q = 0; q < 8; q++) acc[q] = 0ull;
    const ull SU2 = pack2(S_USS, S_USS);
    const ull SW2 = pack2(S_UVV, S_UVV);

    // --- uss: K=4096, k=(i<<6)|j ---
    for (int kb = 0; kb < 4096; kb += 32) {
        const float4* wg = (const float4*)(Wuss + (size_t)kb * 64);
        float4* w4 = (float4*)WsA;
        w4[tid] = wg[tid];
        w4[tid + 256] = wg[tid + 256];
#pragma unroll
        for (int r = 0; r < 4; r++) {
            int lin = tid + r * 256;       // 1024 pair entries
            int kk = lin >> 5, tp = lin & 31;
            int k = kb + kk; int i = k >> 6, j = k & 63;
            ull p = fmul2(fmul2(*(const ull*)(ns_T + i * 64 + 2 * tp),
                                *(const ull*)(as_T + j * 64 + 2 * tp)), SU2);
            float2 pf = unpack2(p);
            ulonglong2 d;
            d.x = pack2(pf.x, pf.x); d.y = pack2(pf.y, pf.y);
            *(ulonglong2*)(AsA + kk * 128 + 4 * tp) = d;
        }
        __syncthreads();
#pragma unroll 8
        for (int kk = 0; kk < 32; kk++) {
            ulonglong2 a2 = *(const ulonglong2*)(AsA + kk * 128 + 4 * ngA);
            ulonglong2 wA = *(const ulonglong2*)(WsA + kk * 64 + 8 * ogA);
            ulonglong2 wB = *(const ulonglong2*)(WsA + kk * 64 + 8 * ogA + 4);
            ffma2(acc[0], a2.x, wA.x); ffma2(acc[1], a2.x, wA.y);
            ffma2(acc[2], a2.x, wB.x); ffma2(acc[3], a2.x, wB.y);
            ffma2(acc[4], a2.y, wA.x); ffma2(acc[5], a2.y, wA.y);
            ffma2(acc[6], a2.y, wB.x); ffma2(acc[7], a2.y, wB.y);
        }
        __syncthreads();
    }
    // --- uvv: K=3*1024, k=(m<<5)|n per x (W shared across x) ---
    for (int kb = 0; kb < 3072; kb += 32) {
        const int xx = kb >> 10, km = kb & 1023;
        const float4* wg = (const float4*)(Wuvv + (size_t)km * 64);
        float4* w4 = (float4*)WsA;
        w4[tid] = wg[tid];
        w4[tid + 256] = wg[tid + 256];
#pragma unroll
        for (int r = 0; r < 4; r++) {
            int lin = tid + r * 256;
            int kk = lin >> 5, tp = lin & 31;
            int k = km + kk; int m = k >> 5, n = k & 31;
            ull p = fmul2(fmul2(*(const ull*)(nv_T + (xx * 32 + m) * 64 + 2 * tp),
                                *(const ull*)(av_T + (xx * 32 + n) * 64 + 2 * tp)), SW2);
            float2 pf = unpack2(p);
            ulonglong2 d;
            d.x = pack2(pf.x, pf.x); d.y = pack2(pf.y, pf.y);
            *(ulonglong2*)(AsA + kk * 128 + 4 * tp) = d;
        }
        __syncthreads();
#pragma unroll 8
        for (int kk = 0; kk < 32; kk++) {
            ulonglong2 a2 = *(const ulonglong2*)(AsA + kk * 128 + 4 * ngA);
            ulonglong2 wA = *(const ulonglong2*)(WsA + kk * 64 + 8 * ogA);
            ulonglong2 wB = *(const ulonglong2*)(WsA + kk * 64 + 8 * ogA + 4);
            ffma2(acc[0], a2.x, wA.x); ffma2(acc[1], a2.x, wA.y);
            ffma2(acc[2], a2.x, wB.x); ffma2(acc[3], a2.x, wB.y);
            ffma2(acc[4], a2.y, wA.x); ffma2(acc[5], a2.y, wA.y);
            ffma2(acc[6], a2.y, wB.x); ffma2(acc[7], a2.y, wB.y);
        }
        __syncthreads();
    }
    // u_s epilogue: silu + residual -> g_ns (ns_T stays intact for phase B)
#pragma unroll
    for (int n = 0; n < 2; n++) {
        int t = 2 * ngA + n;
        float* gp = g_ns + (size_t)(node0 + t) * 64;
#pragma unroll
        for (int op = 0; op < 4; op++) {
            float2 u = unpack2(acc[n * 4 + op]);
            int o0 = 8 * ogA + 2 * op;
            float2 w;
            w.x = ns_T[o0 * 64 + t] + u.x * sigmf(u.x);
            w.y = ns_T[(o0 + 1) * 64 + t] + u.y * sigmf(u.y);
            *(float2*)(gp + o0) = w;
        }
    }

    // ================ Phase B: u_v = usv + uvs ================
    // rows = pair-row pr = x*32 + tp (96), outs 32. thread: outs 2*ogB..+1, prs 6*pgB..+5
    const int ogB = tid & 15;
    const int pgB = tid >> 4;
    float* WsB = scr;            // [32 kk][32 o]
    float* AsB = scr + 1024;     // [32 kk][192 = 96 pairs f32x2]
    ull vac[12];
#pragma unroll
    for (int q = 0; q < 12; q++) vac[q] = 0ull;
    const ull SV2 = pack2(S_V, S_V);

    // --- usv: K=2048, k=(i<<5)|n; A = ns[t,i]*av[t,n,x] ---
    for (int kb = 0; kb < 2048; kb += 32) {
        const float4* wg = (const float4*)(Wusv + (size_t)kb * 32);
        ((float4*)WsB)[tid] = wg[tid];
#pragma unroll
        for (int r = 0; r < 12; r++) {
            int lin = tid + r * 256;       // 3072 pair entries
            int kk = lin / 96, pr = lin % 96;
            int x = pr >> 5, tp = pr & 31;
            int k = kb + kk; int i = k >> 5, n = k & 31;
            *(ull*)(AsB + kk * 192 + 2 * pr) =
                fmul2(fmul2(*(const ull*)(ns_T + i * 64 + 2 * tp),
                            *(const ull*)(av_T + (x * 32 + n) * 64 + 2 * tp)), SV2);
        }
        __syncthreads();
#pragma unroll 4
        for (int kk = 0; kk < 32; kk++) {
            const float* ab = AsB + kk * 192 + 12 * pgB;
            ulonglong2 a01 = *(const ulonglong2*)(ab);
            ulonglong2 a23 = *(const ulonglong2*)(ab + 4);
            ulonglong2 a45 = *(const ulonglong2*)(ab + 8);
            float2 wf = *(const float2*)(WsB + kk * 32 + 2 * ogB);
            ull w0 = pack2(wf.x, wf.x), w1 = pack2(wf.y, wf.y);
            ffma2(vac[0],  a01.x, w0); ffma2(vac[1],  a01.x, w1);
            ffma2(vac[2],  a01.y, w0); ffma2(vac[3],  a01.y, w1);
            ffma2(vac[4],  a23.x, w0); ffma2(vac[5],  a23.x, w1);
            ffma2(vac[6],  a23.y, w0); ffma2(vac[7],  a23.y, w1);
            ffma2(vac[8],  a45.x, w0); ffma2(vac[9],  a45.x, w1);
            ffma2(vac[10], a45.y, w0); ffma2(vac[11], a45.y, w1);
        }
        __syncthreads();
    }
    // --- uvs: K=2048, k=(m<<6)|j; A = nv[t,m,x]*as[t,j] ---
    for (int kb = 0; kb < 2048; kb += 32) {
        const float4* wg = (const float4*)(Wuvs + (size_t)kb * 32);
        ((float4*)WsB)[tid] = wg[tid];
#pragma unroll
        for (int r = 0; r < 12; r++) {
            int lin = tid + r * 256;
            int kk = lin / 96, pr = lin % 96;
            int x = pr >> 5, tp = pr & 31;
            int k = kb + kk; int m = k >> 6, j = k & 63;
            *(ull*)(AsB + kk * 192 + 2 * pr) =
                fmul2(fmul2(*(const ull*)(nv_T + (x * 32 + m) * 64 + 2 * tp),
                            *(const ull*)(as_T + j * 64 + 2 * tp)), SV2);
        }
        __syncthreads();
#pragma unroll 4
        for (int kk = 0; kk < 32; kk++) {
            const float* ab = AsB + kk * 192 + 12 * pgB;
            ulonglong2 a01 = *(const ulonglong2*)(ab);
            ulonglong2 a23 = *(const ulonglong2*)(ab + 4);
            ulonglong2 a45 = *(const ulonglong2*)(ab + 8);
            float2 wf = *(const float2*)(WsB + kk * 32 + 2 * ogB);
            ull w0 = pack2(wf.x, wf.x), w1 = pack2(wf.y, wf.y);
            ffma2(vac[0],  a01.x, w0); ffma2(vac[1],  a01.x, w1);
            ffma2(vac[2],  a01.y, w0); ffma2(vac[3],  a01.y, w1);
            ffma2(vac[4],  a23.x, w0); ffma2(vac[5],  a23.x, w1);
            ffma2(vac[6],  a23.y, w0); ffma2(vac[7],  a23.y, w1);
            ffma2(vac[8],  a45.x, w0); ffma2(vac[9],  a45.x, w1);
            ffma2(vac[10], a45.y, w0); ffma2(vac[11], a45.y, w1);
        }
        __syncthreads();
    }

    // ---- gate mean: reduce over outs (16 threads = half-warp) then over x via smem ----
    {
        ull* sred = (ull*)scr;   // 96 pair-sums (f32x2 over node pair)
        ull part[6];
#pragma unroll
        for (int j = 0; j < 6; j++) part[j] = fadd2(vac[2 * j], vac[2 * j + 1]);
#pragma unroll
        for (int d = 1; d < 16; d <<= 1) {
#pragma unroll
            for (int j = 0; j < 6; j++)
                part[j] = fadd2(part[j], __shfl_xor_sync(0xffffffffu, part[j], d));
        }
        if ((tid & 15) == 0) {
#pragma unroll
            for (int j = 0; j < 6; j++) sred[6 * pgB + j] = part[j];
        }
        __syncthreads();

        // epilogue: gate + residual -> g_nv
#pragma unroll
        for (int j = 0; j < 6; j++) {
            int pr = 6 * pgB + j;
            int x = pr >> 5, tp = pr & 31;
            ull s = fadd2(fadd2(sred[tp], sred[32 + tp]), sred[64 + tp]);
            float2 m2 = unpack2(s);
            float mean0 = m2.x * (1.0f / 96.0f);
            float mean1 = m2.y * (1.0f / 96.0f);
            int t0 = 2 * tp;
#pragma unroll
            for (int oi = 0; oi < 2; oi++) {
                int o = 2 * ogB + oi;
                int f = o * 3 + x;
                float gw = __ldg(guw + f), gb = __ldg(gub + f);
                float2 u = unpack2(vac[2 * j + oi]);
                float gg0 = sigmf(mean0 * gw + gb);
                float gg1 = sigmf(mean1 * gw + gb);
                g_nv[(size_t)(node0 + t0) * 96 + f]     = nv_T[(x * 32 + o) * 64 + t0] + u.x * gg0;
                g_nv[(size_t)(node0 + t0 + 1) * 96 + f] = nv_T[(x * 32 + o) * 64 + t0 + 1] + u.y * gg1;
            }
        }
    }
}

// ============================ k_out: out = ns @ W_out / 8 ============================
__global__ __launch_bounds__(256) void k_out(const float* __restrict__ Wout,
                                             float* __restrict__ out) {
    __shared__ float s_w[32 * 256];
    __shared__ float s_ns[16 * 64];
    const int tid = threadIdx.x;
    const int node0 = blockIdx.x * 16;
#pragma unroll
    for (int r = 0; r < 4; r++) {
        int lin = tid + r * 256; int t = lin >> 6, i = lin & 63;
        s_ns[t * 64 + i] = g_ns[(size_t)(node0 + t) * 64 + i];
    }
    float acc[16];
#pragma unroll
    for (int t = 0; t < 16; t++) acc[t] = 0.f;
    for (int ic = 0; ic < 2; ic++) {
        __syncthreads();
        const float4* wg = (const float4*)(Wout + (size_t)ic * 32 * 256);
        float4* ws4 = (float4*)s_w;
#pragma unroll
        for (int r = 0; r < 8; r++) ws4[tid + r * 256] = wg[tid + r * 256];
        __syncthreads();
#pragma unroll 8
        for (int i = 0; i < 32; i++) {
            float w = s_w[i * 256 + tid];
#pragma unroll
            for (int t = 0; t < 16; t++) acc[t] += s_ns[t * 64 + ic * 32 + i] * w;
        }
    }
#pragma unroll
    for (int t = 0; t < 16; t++)
        out[(size_t)(node0 + t) * 256 + tid] = acc[t] * INV8;
}

// =====================================================================================
extern "C" void kernel_launch(void* const* d_in, const int* in_sizes, int n_in,
                              void* d_out, int out_size) {
    const float* x    = (const float*)d_in[0];
    const float* eattr= (const float*)d_in[1];
    const float* Win  = (const float*)d_in[2];
    const float* Wout = (const float*)d_in[3];
    const float* Wss  = (const float*)d_in[4];
    const float* Wvv0 = (const float*)d_in[5];
    const float* Wsv  = (const float*)d_in[6];
    const float* Wvs  = (const float*)d_in[7];
    const float* gmw  = (const float*)d_in[8];
    const float* gmb  = (const float*)d_in[9];
    const float* Wuss = (const float*)d_in[10];
    const float* Wuvv = (const float*)d_in[11];
    const float* Wusv = (const float*)d_in[12];
    const float* Wuvs = (const float*)d_in[13];
    const float* guw  = (const float*)d_in[14];
    const float* gub  = (const float*)d_in[15];
    const int*   eidx = (const int*)d_in[16];
    float* out = (float*)d_out;

    void *p_nv = 0, *p_as = 0, *p_av = 0;
    cudaGetSymbolAddress(&p_nv, g_nv);
    cudaGetSymbolAddress(&p_as, g_as);
    cudaGetSymbolAddress(&p_av, g_av);

    cudaFuncSetAttribute(k_bilin, cudaFuncAttributeMaxDynamicSharedMemorySize, BILIN_SMEM);

    cudaMemsetAsync(p_nv, 0, sizeof(float) * NN * 96, 0);
    k_in<<<NN / 32, 256>>>(x, Win);

    for (int l = 0; l < 2; l++) {
        k_feat<<<NN / 8, 256>>>(Wss + l * 4096, Wvv0 + l * 2048,
                                Wsv + l * 2048, Wvs + l * 1024);
        cudaMemsetAsync(p_as, 0, sizeof(float) * NN * 64, 0);
        cudaMemsetAsync(p_av, 0, sizeof(float) * NN * 96, 0);
        k_edge<<<EE / 8, 256>>>(eattr, eidx, gmw + l * 96, gmb + l * 96);
        k_bilin<<<NN / 64, 256, BILIN_SMEM>>>(Wuss + (size_t)l * 262144,
                                              Wuvv + (size_t)l * 65536,
                                              Wusv + (size_t)l * 65536,
                                              Wuvs + (size_t)l * 65536,
                                              guw + l * 96, gub + l * 96);
    }
    k_out<<<NN / 16, 256>>>(Wout, out);
}

// round 10
// speedup vs baseline: 1.5785x; 1.5785x over previous
#include <cuda_runtime.h>
#include <math.h>
#include <stdint.h>

#define NN   32768
#define EE   1048576
#define NSD  64
#define NVD  32
#define LATD 256

// ---- scales ----
#define INV8    0.125f                 // 1/sqrt(64)
#define C1      0.10206207261596575f   // (1/sqrt(3))/sqrt(32) = 1/sqrt(96)
#define INV_R2  0.7071067811865476f
#define INVS32  0.17677669529663687f   // 1/sqrt(32)
#define S_USS   0.011048543456039806f  // 1/(64*sqrt(2))
#define S_UVV   0.012757998811063534f  // 1/(32*sqrt(6))
#define S_V     0.015625f              // 1/sqrt(64*32*2) = 1/64

typedef unsigned long long ull;

// ---- scratch (device globals; no allocation) ----
__device__ float g_ns[NN * NSD];
__device__ float g_nv[NN * NVD * 3];
__device__ float g_NF[(size_t)NN * 384];  // SS(64)|Q(3x64)|SV(32)|VS(3x32)
__device__ float g_as[NN * NSD];
__device__ float g_av[NN * NVD * 3];

__device__ __forceinline__ float sigmf(float x) { return 1.0f / (1.0f + __expf(-x)); }

// ---- packed f32x2 helpers ----
__device__ __forceinline__ void ffma2(ull& d, ull a, ull b) {
    asm("fma.rn.f32x2 %0, %1, %2, %0;" : "+l"(d) : "l"(a), "l"(b));
}
__device__ __forceinline__ ull fadd2(ull a, ull b) {
    ull r; asm("add.rn.f32x2 %0, %1, %2;" : "=l"(r) : "l"(a), "l"(b)); return r;
}
__device__ __forceinline__ ull pack2(float x, float y) {
    ull r;
    asm("mov.b64 %0, {%1, %2};" : "=l"(r)
        : "r"(__float_as_uint(x)), "r"(__float_as_uint(y)));
    return r;
}
__device__ __forceinline__ float2 unpack2(ull v) {
    unsigned int lo, hi;
    asm("mov.b64 {%0, %1}, %2;" : "=r"(lo), "=r"(hi) : "l"(v));
    return make_float2(__uint_as_float(lo), __uint_as_float(hi));
}

// ============================ k_in: ns = x @ W_in / 8 ============================
__global__ __launch_bounds__(256) void k_in(const float* __restrict__ x,
                                            const float* __restrict__ Win) {
    __shared__ float xs[32 * 65];
    __shared__ float ws[64 * 64];
    const int tid = threadIdx.x;
    const int node0 = blockIdx.x * 32;
    const float4* wg = (const float4*)Win;
    float4* ws4 = (float4*)ws;
#pragma unroll
    for (int r = 0; r < 4; r++) ws4[tid + r * 256] = wg[tid + r * 256];
#pragma unroll
    for (int r = 0; r < 8; r++) {
        int lin = tid + r * 256; int t = lin >> 6, i = lin & 63;
        xs[t * 65 + i] = x[(size_t)(node0 + t) * 64 + i];
    }
    __syncthreads();
    const int o = tid & 63, tq = tid >> 6;
    float acc[8] = {0, 0, 0, 0, 0, 0, 0, 0};
#pragma unroll 16
    for (int i = 0; i < 64; i++) {
        float w = ws[i * 64 + o];
#pragma unroll
        for (int tt = 0; tt < 8; tt++) acc[tt] += xs[(tq * 8 + tt) * 65 + i] * w;
    }
#pragma unroll
    for (int tt = 0; tt < 8; tt++)
        g_ns[(size_t)(node0 + tq * 8 + tt) * 64 + o] = acc[tt] * INV8;
}

// ============== k_feat: per-node precompute SS, Q, SV, VS ==============
__global__ __launch_bounds__(256) void k_feat(const float* __restrict__ Wss,
                                              const float* __restrict__ Wvv0,
                                              const float* __restrict__ Wsv,
                                              const float* __restrict__ Wvs) {
    __shared__ float s_wss[64 * 64];
    __shared__ float s_wvv[32 * 64];
    __shared__ float s_wsv[64 * 32];
    __shared__ float s_wvs[32 * 32];
    __shared__ float s_ns[8][64];
    __shared__ float s_nv[8][96];
    const int tid = threadIdx.x;
    for (int i = tid; i < 4096; i += 256) s_wss[i] = Wss[i];
    for (int i = tid; i < 2048; i += 256) s_wvv[i] = Wvv0[i];
    for (int i = tid; i < 2048; i += 256) s_wsv[i] = Wsv[i];
    for (int i = tid; i < 1024; i += 256) s_wvs[i] = Wvs[i];
    const int w = tid >> 5, lane = tid & 31;
    const int node = blockIdx.x * 8 + w;
#pragma unroll
    for (int r = 0; r < 2; r++) s_ns[w][lane + 32 * r] = g_ns[(size_t)node * 64 + lane + 32 * r];
#pragma unroll
    for (int r = 0; r < 3; r++) s_nv[w][lane + 32 * r] = g_nv[(size_t)node * 96 + lane + 32 * r];
    __syncthreads();
    float* nf = g_NF + (size_t)node * 384;
#pragma unroll
    for (int h = 0; h < 2; h++) {
        int o = lane + 32 * h;
        float a = 0;
#pragma unroll 8
        for (int i = 0; i < 64; i++) a += s_ns[w][i] * s_wss[i * 64 + o];
        nf[o] = a;
    }
#pragma unroll
    for (int xx = 0; xx < 3; xx++) {
#pragma unroll
        for (int h = 0; h < 2; h++) {
            int o = lane + 32 * h;
            float a = 0;
#pragma unroll 8
            for (int m = 0; m < 32; m++) a += s_nv[w][m * 3 + xx] * s_wvv[m * 64 + o];
            nf[64 + xx * 64 + o] = a;
        }
    }
    {
        float a = 0;
#pragma unroll 8
        for (int i = 0; i < 64; i++) a += s_ns[w][i] * s_wsv[i * 32 + lane];
        nf[256 + lane] = a;
    }
#pragma unroll
    for (int xx = 0; xx < 3; xx++) {
        float a = 0;
#pragma unroll 8
        for (int m = 0; m < 32; m++) a += s_nv[w][m * 3 + xx] * s_wvs[m * 32 + lane];
        nf[288 + xx * 32 + lane] = a;
    }
}

// ================= k_edge: per-edge message + gate + scatter-add =================
__global__ __launch_bounds__(256) void k_edge(const float* __restrict__ eattr,
                                              const int* __restrict__ eidx,
                                              const float* __restrict__ gmw,
                                              const float* __restrict__ gmb) {
    __shared__ float s_gw[96], s_gb[96];
    const int tid = threadIdx.x;
    if (tid < 96) { s_gw[tid] = gmw[tid]; s_gb[tid] = gmb[tid]; }
    __syncthreads();
    const int w = tid >> 5, lane = tid & 31;
    const int e = blockIdx.x * 8 + w;
    const int r = eidx[e];
    const int c = eidx[EE + e];
    const float ev0 = eattr[(size_t)e * 4 + 0];
    const float ev1 = eattr[(size_t)e * 4 + 1];
    const float ev2 = eattr[(size_t)e * 4 + 2];
    const float es  = eattr[(size_t)e * 4 + 3];
    const float* nf = g_NF + (size_t)c * 384;
    float ms[2];
#pragma unroll
    for (int h = 0; h < 2; h++) {
        int o = lane + 32 * h;
        float dot = ev0 * nf[64 + o] + ev1 * nf[128 + o] + ev2 * nf[192 + o];
        float v = (es * nf[o] * INV8 + dot * C1) * INV_R2;
        ms[h] = v * sigmf(v);
    }
    const float sv = nf[256 + lane];
    float mv0 = (sv * ev0 * INV8 + es * nf[288 + lane] * INVS32) * INV_R2;
    float mv1 = (sv * ev1 * INV8 + es * nf[320 + lane] * INVS32) * INV_R2;
    float mv2 = (sv * ev2 * INV8 + es * nf[352 + lane] * INVS32) * INV_R2;
    float p = mv0 + mv1 + mv2;
#pragma unroll
    for (int off = 16; off; off >>= 1) p += __shfl_xor_sync(0xffffffffu, p, off);
    const float mean = p * (1.0f / 96.0f);
    const float g0 = sigmf(mean * s_gw[lane * 3 + 0] + s_gb[lane * 3 + 0]);
    const float g1 = sigmf(mean * s_gw[lane * 3 + 1] + s_gb[lane * 3 + 1]);
    const float g2 = sigmf(mean * s_gw[lane * 3 + 2] + s_gb[lane * 3 + 2]);
    float* as = g_as + (size_t)r * 64;
    float* av = g_av + (size_t)r * 96;
    atomicAdd(as + lane,        ms[0]);
    atomicAdd(as + lane + 32,   ms[1]);
    atomicAdd(av + lane * 3 + 0, mv0 * g0);
    atomicAdd(av + lane * 3 + 1, mv1 * g1);
    atomicAdd(av + lane * 3 + 2, mv2 * g2);
}

// ====== k_bilin: four bilinears + gate + residual ======
// 64 nodes / block, 256 threads. R7-proven inner loop (f32x2 acc over node pairs,
// W packed via movs per kk), kb=32 chunking to shrink smem -> 2 blocks/SM.
// smem floats: ns 4160 | as 4160 | nv 6208 | av 6208 | scr 7168 = 27904 (109KB)
#define BILIN_SMEM (27904 * 4)

__global__ __launch_bounds__(256, 2) void k_bilin(const float* __restrict__ Wuss,
                                                  const float* __restrict__ Wuvv,
                                                  const float* __restrict__ Wusv,
                                                  const float* __restrict__ Wuvs,
                                                  const float* __restrict__ guw,
                                                  const float* __restrict__ gub) {
    extern __shared__ float sm[];
    float* ns_s = sm;                 // [64][65]
    float* as_s = sm + 4160;          // [64][65]
    float* nv_s = sm + 8320;          // [64][97]
    float* av_s = sm + 14528;         // [64][97]
    float* scr  = sm + 20736;         // 7168 floats (W + A staging, reused per phase)
    const int tid = threadIdx.x;
    const int node0 = blockIdx.x * 64;

    // ---- load node data (vectorized, row-major with conflict-free strides) ----
    {
        const float4* gns = (const float4*)(g_ns + (size_t)node0 * 64);
        const float4* gas = (const float4*)(g_as + (size_t)node0 * 64);
#pragma unroll
        for (int r = 0; r < 4; r++) {
            int lin = tid + r * 256; int t = lin >> 4, c = lin & 15;
            float4 v = gns[lin];
            float4 u = gas[lin];
            float* pd = ns_s + t * 65 + c * 4;
            pd[0] = v.x; pd[1] = v.y; pd[2] = v.z; pd[3] = v.w;
            float* qd = as_s + t * 65 + c * 4;
            qd[0] = u.x; qd[1] = u.y; qd[2] = u.z; qd[3] = u.w;
        }
        const float4* gnv = (const float4*)(g_nv + (size_t)node0 * 96);
        const float4* gav = (const float4*)(g_av + (size_t)node0 * 96);
#pragma unroll
        for (int r = 0; r < 6; r++) {
            int lin = tid + r * 256; int t = lin / 24, c = lin % 24;
            float4 v = gnv[lin];
            float4 u = gav[lin];
            float* pd = nv_s + t * 97 + c * 4;
            pd[0] = v.x; pd[1] = v.y; pd[2] = v.z; pd[3] = v.w;
            float* qd = av_s + t * 97 + c * 4;
            qd[0] = u.x; qd[1] = u.y; qd[2] = u.z; qd[3] = u.w;
        }
    }
    __syncthreads();

    // ================ Phase A: u_s = uss + uvv ================
    // thread tile: 4 outs (tx) x 4 nodes (ty, as 2 f32x2 pairs)
    const int tx = tid & 15, ty = tid >> 4;
    float* W_s = scr;            // [32][64], pre-scaled
    float* A_s = scr + 2048;     // [32][64]
    ull acc[8];
#pragma unroll
    for (int q = 0; q < 8; q++) acc[q] = 0ull;

    // --- uss: K = 4096, A[t,k] = ns[t,i]*as[t,j], k=(i<<6)|j ---
    for (int kb = 0; kb < 4096; kb += 32) {
        const float4* wg = (const float4*)(Wuss + (size_t)kb * 64);
        float4* ws4 = (float4*)W_s;
#pragma unroll
        for (int rr = 0; rr < 2; rr++) {
            float4 w = wg[tid + rr * 256];
            w.x *= S_USS; w.y *= S_USS; w.z *= S_USS; w.w *= S_USS;
            ws4[tid + rr * 256] = w;
        }
#pragma unroll
        for (int rr = 0; rr < 8; rr++) {
            int lin = tid + rr * 256; int kk = lin >> 6, t = lin & 63;
            int k = kb + kk; int i = k >> 6, j = k & 63;
            A_s[kk * 64 + t] = ns_s[t * 65 + i] * as_s[t * 65 + j];
        }
        __syncthreads();
#pragma unroll 8
        for (int kk = 0; kk < 32; kk++) {
            ulonglong2 a2 = *(const ulonglong2*)(A_s + kk * 64 + ty * 4);
            float4 w4 = *(const float4*)(W_s + kk * 64 + tx * 4);
            ull wx = pack2(w4.x, w4.x), wy = pack2(w4.y, w4.y);
            ull wz = pack2(w4.z, w4.z), ww = pack2(w4.w, w4.w);
            ffma2(acc[0], a2.x, wx); ffma2(acc[1], a2.x, wy);
            ffma2(acc[2], a2.x, wz); ffma2(acc[3], a2.x, ww);
            ffma2(acc[4], a2.y, wx); ffma2(acc[5], a2.y, wy);
            ffma2(acc[6], a2.y, wz); ffma2(acc[7], a2.y, ww);
        }
        __syncthreads();
    }
    // --- uvv: K = 3*1024 (x outer), A = nv[t,m,x]*av[t,n,x], k=(m<<5)|n ---
    for (int kb = 0; kb < 3072; kb += 32) {
        int xx = kb >> 10, km = kb & 1023;
        const float4* wg = (const float4*)(Wuvv + (size_t)km * 64);
        float4* ws4 = (float4*)W_s;
#pragma unroll
        for (int rr = 0; rr < 2; rr++) {
            float4 w = wg[tid + rr * 256];
            w.x *= S_UVV; w.y *= S_UVV; w.z *= S_UVV; w.w *= S_UVV;
            ws4[tid + rr * 256] = w;
        }
#pragma unroll
        for (int rr = 0; rr < 8; rr++) {
            int lin = tid + rr * 256; int kk = lin >> 6, t = lin & 63;
            int k = km + kk; int m = k >> 5, n = k & 31;
            A_s[kk * 64 + t] = nv_s[t * 97 + m * 3 + xx] * av_s[t * 97 + n * 3 + xx];
        }
        __syncthreads();
#pragma unroll 8
        for (int kk = 0; kk < 32; kk++) {
            ulonglong2 a2 = *(const ulonglong2*)(A_s + kk * 64 + ty * 4);
            float4 w4 = *(const float4*)(W_s + kk * 64 + tx * 4);
            ull wx = pack2(w4.x, w4.x), wy = pack2(w4.y, w4.y);
            ull wz = pack2(w4.z, w4.z), ww = pack2(w4.w, w4.w);
            ffma2(acc[0], a2.x, wx); ffma2(acc[1], a2.x, wy);
            ffma2(acc[2], a2.x, wz); ffma2(acc[3], a2.x, ww);
            ffma2(acc[4], a2.y, wx); ffma2(acc[5], a2.y, wy);
            ffma2(acc[6], a2.y, wz); ffma2(acc[7], a2.y, ww);
        }
        __syncthreads();
    }
    // u_s epilogue: silu + residual -> global ns (smem ns_s stays intact for phase B)
#pragma unroll
    for (int g = 0; g < 2; g++) {
#pragma unroll
        for (int q = 0; q < 4; q++) {
            float2 u = unpack2(acc[g * 4 + q]);
            int o = tx * 4 + q;
            int t0 = ty * 4 + g * 2;
            float s0 = u.x * sigmf(u.x);
            float s1 = u.y * sigmf(u.y);
            g_ns[(size_t)(node0 + t0) * 64 + o]     = ns_s[t0 * 65 + o] + s0;
            g_ns[(size_t)(node0 + t0 + 1) * 64 + o] = ns_s[(t0 + 1) * 65 + o] + s1;
        }
    }

    // ================ Phase B: u_v = usv + uvs ================
    // thread tile: 4 outs (txB) x 2 nodes (f32x2 pair, tyB) x 3 x-components
    const int txB = tid & 7, tyB = tid >> 3;
    float* WB = scr;             // [32][32], pre-scaled
    float* AB = scr + 1024;      // [3][32][64]
    ull vacc[12];
#pragma unroll
    for (int q = 0; q < 12; q++) vacc[q] = 0ull;

    // --- usv: K = 2048 per x, A(x)[t,k] = ns[t,i]*av[t,n,x], k=(i<<5)|n ---
    for (int kb = 0; kb < 2048; kb += 32) {
        {
            float4 w = ((const float4*)(Wusv + (size_t)kb * 32))[tid];
            w.x *= S_V; w.y *= S_V; w.z *= S_V; w.w *= S_V;
            ((float4*)WB)[tid] = w;
        }
#pragma unroll
        for (int rr = 0; rr < 24; rr++) {
            int lin = tid + rr * 256;
            int xx = lin >> 11; int rem = lin & 2047; int kk = rem >> 6, t = rem & 63;
            int k = kb + kk; int i = k >> 5, n = k & 31;
            AB[xx * 2048 + kk * 64 + t] = ns_s[t * 65 + i] * av_s[t * 97 + n * 3 + xx];
        }
        __syncthreads();
#pragma unroll 8
        for (int kk = 0; kk < 32; kk++) {
            float4 w4 = *(const float4*)(WB + kk * 32 + txB * 4);
            ull w0 = pack2(w4.x, w4.x), w1 = pack2(w4.y, w4.y);
            ull w2 = pack2(w4.z, w4.z), w3 = pack2(w4.w, w4.w);
            ull a0 = *(const ull*)(AB + kk * 64 + tyB * 2);
            ull a1 = *(const ull*)(AB + 2048 + kk * 64 + tyB * 2);
            ull a2 = *(const ull*)(AB + 4096 + kk * 64 + tyB * 2);
            ffma2(vacc[0],  a0, w0); ffma2(vacc[1],  a0, w1);
            ffma2(vacc[2],  a0, w2); ffma2(vacc[3],  a0, w3);
            ffma2(vacc[4],  a1, w0); ffma2(vacc[5],  a1, w1);
            ffma2(vacc[6],  a1, w2); ffma2(vacc[7],  a1, w3);
            ffma2(vacc[8],  a2, w0); ffma2(vacc[9],  a2, w1);
            ffma2(vacc[10], a2, w2); ffma2(vacc[11], a2, w3);
        }
        __syncthreads();
    }
    // --- uvs: K = 2048 per x, A(x)[t,k] = nv[t,m,x]*as[t,j], k=(m<<6)|j ---
    for (int kb = 0; kb < 2048; kb += 32) {
        {
            float4 w = ((const float4*)(Wuvs + (size_t)kb * 32))[tid];
            w.x *= S_V; w.y *= S_V; w.z *= S_V; w.w *= S_V;
            ((float4*)WB)[tid] = w;
        }
#pragma unroll
        for (int rr = 0; rr < 24; rr++) {
            int lin = tid + rr * 256;
            int xx = lin >> 11; int rem = lin & 2047; int kk = rem >> 6, t = rem & 63;
            int k = kb + kk; int m = k >> 6, j = k & 63;
            AB[xx * 2048 + kk * 64 + t] = nv_s[t * 97 + m * 3 + xx] * as_s[t * 65 + j];
        }
        __syncthreads();
#pragma unroll 8
        for (int kk = 0; kk < 32; kk++) {
            float4 w4 = *(const float4*)(WB + kk * 32 + txB * 4);
            ull w0 = pack2(w4.x, w4.x), w1 = pack2(w4.y, w4.y);
            ull w2 = pack2(w4.z, w4.z), w3 = pack2(w4.w, w4.w);
            ull a0 = *(const ull*)(AB + kk * 64 + tyB * 2);
            ull a1 = *(const ull*)(AB + 2048 + kk * 64 + tyB * 2);
            ull a2 = *(const ull*)(AB + 4096 + kk * 64 + tyB * 2);
            ffma2(vacc[0],  a0, w0); ffma2(vacc[1],  a0, w1);
            ffma2(vacc[2],  a0, w2); ffma2(vacc[3],  a0, w3);
            ffma2(vacc[4],  a1, w0); ffma2(vacc[5],  a1, w1);
            ffma2(vacc[6],  a1, w2); ffma2(vacc[7],  a1, w3);
            ffma2(vacc[8],  a2, w0); ffma2(vacc[9],  a2, w1);
            ffma2(vacc[10], a2, w2); ffma2(vacc[11], a2, w3);
        }
        __syncthreads();
    }

    // u_v epilogue: mean over 96 per node (8 threads share pair tyB), gate, residual
    {
        ull psum = vacc[0];
#pragma unroll
        for (int q = 1; q < 12; q++) psum = fadd2(psum, vacc[q]);
        psum = fadd2(psum, __shfl_xor_sync(0xffffffffu, psum, 1));
        psum = fadd2(psum, __shfl_xor_sync(0xffffffffu, psum, 2));
        psum = fadd2(psum, __shfl_xor_sync(0xffffffffu, psum, 4));
        float2 pm = unpack2(psum);
        const float mean0 = pm.x * (1.0f / 96.0f);
        const float mean1 = pm.y * (1.0f / 96.0f);
        const int n0 = tyB * 2;
#pragma unroll
        for (int xx = 0; xx < 3; xx++) {
#pragma unroll
            for (int q = 0; q < 4; q++) {
                int o = txB * 4 + q; int idx = o * 3 + xx;
                float gw = __ldg(guw + idx), gb = __ldg(gub + idx);
                float2 u = unpack2(vacc[xx * 4 + q]);
                float g0 = sigmf(mean0 * gw + gb);
                float g1 = sigmf(mean1 * gw + gb);
                g_nv[(size_t)(node0 + n0) * 96 + idx]     = nv_s[n0 * 97 + idx] + u.x * g0;
                g_nv[(size_t)(node0 + n0 + 1) * 96 + idx] = nv_s[(n0 + 1) * 97 + idx] + u.y * g1;
            }
        }
    }
}

// ============================ k_out: out = ns @ W_out / 8 ============================
__global__ __launch_bounds__(256) void k_out(const float* __restrict__ Wout,
                                             float* __restrict__ out) {
    __shared__ float s_w[32 * 256];
    __shared__ float s_ns[16 * 64];
    const int tid = threadIdx.x;
    const int node0 = blockIdx.x * 16;
#pragma unroll
    for (int r = 0; r < 4; r++) {
        int lin = tid + r * 256; int t = lin >> 6, i = lin & 63;
        s_ns[t * 64 + i] = g_ns[(size_t)(node0 + t) * 64 + i];
    }
    float acc[16];
#pragma unroll
    for (int t = 0; t < 16; t++) acc[t] = 0.f;
    for (int ic = 0; ic < 2; ic++) {
        __syncthreads();
        const float4* wg = (const float4*)(Wout + (size_t)ic * 32 * 256);
        float4* ws4 = (float4*)s_w;
#pragma unroll
        for (int r = 0; r < 8; r++) ws4[tid + r * 256] = wg[tid + r * 256];
        __syncthreads();
#pragma unroll 8
        for (int i = 0; i < 32; i++) {
            float w = s_w[i * 256 + tid];
#pragma unroll
            for (int t = 0; t < 16; t++) acc[t] += s_ns[t * 64 + ic * 32 + i] * w;
        }
    }
#pragma unroll
    for (int t = 0; t < 16; t++)
        out[(size_t)(node0 + t) * 256 + tid] = acc[t] * INV8;
}

// =====================================================================================
extern "C" void kernel_launch(void* const* d_in, const int* in_sizes, int n_in,
                              void* d_out, int out_size) {
    const float* x    = (const float*)d_in[0];
    const float* eattr= (const float*)d_in[1];
    const float* Win  = (const float*)d_in[2];
    const float* Wout = (const float*)d_in[3];
    const float* Wss  = (const float*)d_in[4];
    const float* Wvv0 = (const float*)d_in[5];
    const float* Wsv  = (const float*)d_in[6];
    const float* Wvs  = (const float*)d_in[7];
    const float* gmw  = (const float*)d_in[8];
    const float* gmb  = (const float*)d_in[9];
    const float* Wuss = (const float*)d_in[10];
    const float* Wuvv = (const float*)d_in[11];
    const float* Wusv = (const float*)d_in[12];
    const float* Wuvs = (const float*)d_in[13];
    const float* guw  = (const float*)d_in[14];
    const float* gub  = (const float*)d_in[15];
    const int*   eidx = (const int*)d_in[16];
    float* out = (float*)d_out;

    void *p_nv = 0, *p_as = 0, *p_av = 0;
    cudaGetSymbolAddress(&p_nv, g_nv);
    cudaGetSymbolAddress(&p_as, g_as);
    cudaGetSymbolAddress(&p_av, g_av);

    cudaFuncSetAttribute(k_bilin, cudaFuncAttributeMaxDynamicSharedMemorySize, BILIN_SMEM);

    cudaMemsetAsync(p_nv, 0, sizeof(float) * NN * 96, 0);
    k_in<<<NN / 32, 256>>>(x, Win);

    for (int l = 0; l < 2; l++) {
        k_feat<<<NN / 8, 256>>>(Wss + l * 4096, Wvv0 + l * 2048,
                                Wsv + l * 2048, Wvs + l * 1024);
        cudaMemsetAsync(p_as, 0, sizeof(float) * NN * 64, 0);
        cudaMemsetAsync(p_av, 0, sizeof(float) * NN * 96, 0);
        k_edge<<<EE / 8, 256>>>(eattr, eidx, gmw + l * 96, gmb + l * 96);
        k_bilin<<<NN / 64, 256, BILIN_SMEM>>>(Wuss + (size_t)l * 262144,
                                              Wuvv + (size_t)l * 65536,
                                              Wusv + (size_t)l * 65536,
                                              Wuvs + (size_t)l * 65536,
                                              guw + l * 96, gub + l * 96);
    }
    k_out<<<NN / 16, 256>>>(Wout, out);
}